// round 1
// baseline (speedup 1.0000x reference)
#include <cuda_runtime.h>
#include <cstdint>
#include <cstddef>

#define NP 1024
#define NL 32768
#define NU 64
#define NS 32
#define SEG 1024          /* NL/NS */
#define MT 64             /* rows per block in main kernel */
#define KC 64             /* K per chunk */
#define NCHUNK (SEG/KC)   /* 16 */
#define T1 256
#define CHUNK1 (NL/T1)    /* 128 */

__device__ float g_ystart[NP * NS];
__device__ float g_partial[(size_t)NS * NP * NU];

__device__ __forceinline__ float finf()  { return __int_as_float(0x7f800000); }
__device__ __forceinline__ float fninf() { return __int_as_float(0xff800000); }

__device__ __forceinline__ unsigned long long pack2(float lo, float hi) {
    unsigned long long r;
    asm("mov.b64 %0, {%1, %2};" : "=l"(r) : "f"(lo), "f"(hi));
    return r;
}
__device__ __forceinline__ unsigned long long fma2(unsigned long long a,
                                                   unsigned long long b,
                                                   unsigned long long c) {
    unsigned long long d;
    asm("fma.rn.f32x2 %0, %1, %2, %3;" : "=l"(d) : "l"(a), "l"(b), "l"(c));
    return d;
}

// ---------------------------------------------------------------------------
// Kernel 1: per-row clamp-composition scan -> y at the 32 segment boundaries.
// y' = clamp(y, a, b); composition of clamps is a clamp:
//   combine((A,B) then (a,b)) = (clamp(A,a,b), clamp(B,a,b))
// j==0 is the clamp (p0, p0) (output forced to x[p,0], no play_weight).
// ---------------------------------------------------------------------------
__global__ __launch_bounds__(T1) void k_boundary(const float* __restrict__ x,
                                                 const float* __restrict__ pw) {
    int p = blockIdx.x;
    int t = threadIdx.x;
    float w = pw[p];
    const float4* xv = (const float4*)(x + (size_t)p * NL + (size_t)t * CHUNK1);
    float A = fninf(), B = finf();
    int jbase = t * CHUNK1;
    #pragma unroll 4
    for (int i = 0; i < CHUNK1 / 4; ++i) {
        float4 v = xv[i];
        float vv0 = v.x, vv1 = v.y, vv2 = v.z, vv3 = v.w;
        float vva[4] = {vv0, vv1, vv2, vv3};
        #pragma unroll
        for (int e = 0; e < 4; ++e) {
            int j = jbase + i * 4 + e;
            float a = vva[e] * w;
            float b = a + 1.0f;
            if (j == 0) { a = vva[e]; b = vva[e]; }
            A = fminf(fmaxf(A, a), b);
            B = fminf(fmaxf(B, a), b);
        }
    }
    __shared__ float sA[T1], sB[T1];
    sA[t] = A; sB[t] = B;
    __syncthreads();
    if (t < 32) {
        // compose 8 consecutive thread-chunks -> one segment aggregate per lane
        float cA = fninf(), cB = finf();
        #pragma unroll
        for (int c = 0; c < 8; ++c) {
            float a = sA[t * 8 + c], b = sB[t * 8 + c];
            cA = fminf(fmaxf(cA, a), b);
            cB = fminf(fmaxf(cB, a), b);
        }
        // inclusive Hillis-Steele scan with the (non-commutative) clamp compose
        #pragma unroll
        for (int d = 1; d < 32; d <<= 1) {
            float oA = __shfl_up_sync(0xffffffffu, cA, d);
            float oB = __shfl_up_sync(0xffffffffu, cB, d);
            if (t >= d) {
                float nA = fminf(fmaxf(oA, cA), cB);
                float nB = fminf(fmaxf(oB, cA), cB);
                cA = nA; cB = nB;
            }
        }
        // exclusive: prefix of clamps j in [0, s*SEG)
        float eA = __shfl_up_sync(0xffffffffu, cA, 1);
        float eB = __shfl_up_sync(0xffffffffu, cB, 1);
        if (t == 0) { eA = fninf(); eB = finf(); }
        g_ystart[p * NS + t] = fminf(fmaxf(0.0f, eA), eB);
    }
}

// ---------------------------------------------------------------------------
// Kernel 2: fused scan + GEMM over one (64-row tile) x (1024-K segment).
// 64 threads regenerate y values chunk-by-chunk (exact sequential recurrence,
// seeded from g_ystart); all 256 threads run a 4x4 register-tiled GEMM with
// packed f32x2 FMAs. Partials go to deterministic scratch (no atomics).
// ---------------------------------------------------------------------------
__global__ __launch_bounds__(256) void k_main(const float* __restrict__ x,
                                              const float* __restrict__ pw,
                                              const float* __restrict__ kern) {
    __shared__ float ws[KC][NU];   // kernel tile  (16 KB)
    __shared__ float ys[KC][MT];   // scan outputs (16 KB)

    int tile = blockIdx.x;         // 0..15  (row tile)
    int s    = blockIdx.y;         // 0..31  (K segment)
    int tid  = threadIdx.x;
    int r0   = tile * MT;
    int jseg = s * SEG;

    int ro = 4 * (tid & 15);       // rows ro..ro+3
    int co = 4 * (tid >> 4);       // cols co..co+3

    unsigned long long acc[4][2];
    #pragma unroll
    for (int i = 0; i < 4; ++i) { acc[i][0] = 0ull; acc[i][1] = 0ull; }

    // scan-thread state (threads 0..63, one per row)
    float y = 0.0f, w = 1.0f;
    const float* xp = x;           // dummy init
    if (tid < MT) {
        int row = r0 + tid;
        y  = g_ystart[row * NS + s];
        w  = pw[row];
        xp = x + (size_t)row * NL + jseg;
    }

    int kwu = tid & 15;            // u-quad for ws loads
    int kwk = tid >> 4;            // base k row for ws loads

    for (int c = 0; c < NCHUNK; ++c) {
        int j0 = jseg + c * KC;
        __syncthreads();           // prior GEMM done reading ws/ys

        // load kernel tile (all threads): 64x64 floats, fully coalesced
        #pragma unroll
        for (int q = 0; q < 4; ++q) {
            int kk = kwk + 16 * q;
            *(float4*)&ws[kk][kwu * 4] =
                *(const float4*)&kern[(size_t)(j0 + kk) * NU + kwu * 4];
        }

        // scan this chunk (threads 0..63) -> ys[k][r]
        if (tid < MT) {
            const float4* xv = (const float4*)(xp + c * KC);
            #pragma unroll 4
            for (int q = 0; q < KC / 4; ++q) {
                float4 v = xv[q];
                float vva[4] = {v.x, v.y, v.z, v.w};
                #pragma unroll
                for (int e = 0; e < 4; ++e) {
                    int j = j0 + q * 4 + e;
                    float a = vva[e] * w;
                    float b = a + 1.0f;
                    if (j == 0) { a = vva[e]; b = vva[e]; }
                    y = fminf(fmaxf(y, a), b);
                    ys[q * 4 + e][tid] = y;
                }
            }
        }
        __syncthreads();

        // GEMM: 16 FMAs per k per thread, packed as 8 x fma.rn.f32x2
        #pragma unroll 8
        for (int k = 0; k < KC; ++k) {
            float4 yv = *(const float4*)&ys[k][ro];
            float4 wv = *(const float4*)&ws[k][co];
            unsigned long long w01 = pack2(wv.x, wv.y);
            unsigned long long w23 = pack2(wv.z, wv.w);
            float yy[4] = {yv.x, yv.y, yv.z, yv.w};
            #pragma unroll
            for (int i = 0; i < 4; ++i) {
                unsigned long long yb = pack2(yy[i], yy[i]);
                acc[i][0] = fma2(yb, w01, acc[i][0]);
                acc[i][1] = fma2(yb, w23, acc[i][1]);
            }
        }
    }

    // write per-segment partials (deterministic layout [s][p][u])
    #pragma unroll
    for (int i = 0; i < 4; ++i) {
        int p = r0 + ro + i;
        size_t base = ((size_t)s * NP + p) * NU + co;
        *(unsigned long long*)&g_partial[base]     = acc[i][0];
        *(unsigned long long*)&g_partial[base + 2] = acc[i][1];
    }
}

// ---------------------------------------------------------------------------
// Kernel 3: fixed-order reduction over segments + bias + tanh.
// ---------------------------------------------------------------------------
__global__ __launch_bounds__(256) void k_reduce(const float* __restrict__ bias,
                                                float* __restrict__ out) {
    int idx = blockIdx.x * blockDim.x + threadIdx.x;   // 0..65535
    int u = idx & (NU - 1);
    float sum = bias[u];
    #pragma unroll
    for (int s = 0; s < NS; ++s)
        sum += g_partial[(size_t)s * (NP * NU) + idx];
    out[idx] = tanhf(sum);
}

extern "C" void kernel_launch(void* const* d_in, const int* in_sizes, int n_in,
                              void* d_out, int out_size) {
    const float* x    = (const float*)d_in[0];
    const float* pw   = (const float*)d_in[1];
    const float* kern = (const float*)d_in[2];
    const float* bias = (const float*)d_in[3];
    float* out = (float*)d_out;

    k_boundary<<<NP, T1>>>(x, pw);
    k_main<<<dim3(NP / MT, NS), 256>>>(x, pw, kern);
    k_reduce<<<(NP * NU) / 256, 256>>>(bias, out);
}